// round 3
// baseline (speedup 1.0000x reference)
#include <cuda_runtime.h>
#include <cuda_fp16.h>
#include <cstdint>

#define M_TOT 8192
#define N_TOT 4096
#define K_TOT 4096

#define BM 128
#define BN 128
#define BK 32
#define LDA 40    // 32 + 8 pad: conflict-free ldmatrix
#define LDB 136   // 128 + 8 pad: conflict-free ldmatrix
#define NT (K_TOT / BK)   // 128 k-tiles

// Scratch (allocation-free rule: __device__ globals)
__device__ __half WH[(size_t)K_TOT * N_TOT];   // 32 MB dequantized weight, (K,N) row-major
__device__ __half XH[(size_t)M_TOT * K_TOT];   // 64 MB fp16 activations, (M,K) row-major

// ---------------------------------------------------------------------------
// Dequant: one thread per packed qweight word (8 k-values, one n column)
// W[k][n] = (nib(qweight) - (nib(qzeros)+1)) * (qscales - qsz) * qss
// ---------------------------------------------------------------------------
__global__ void dequant_kernel(const int* __restrict__ qweight,
                               const int* __restrict__ qzeros,
                               const int* __restrict__ qscales,
                               const float* __restrict__ qs_zeros,
                               const float* __restrict__ qs_scales,
                               const int* __restrict__ g_idx) {
    int idx = blockIdx.x * blockDim.x + threadIdx.x;     // over (K/8)*N
    int n  = idx % N_TOT;
    int kw = idx / N_TOT;
    if (kw >= K_TOT / 8) return;

    int g = g_idx[kw * 8];                                // all 8 k's share a group (8 | 32)
    int zw = qzeros[g * (N_TOT / 8) + (n >> 3)];
    int z  = ((zw >> ((n & 7) * 4)) & 0xF) + 1;
    float scale = ((float)qscales[g * N_TOT + n] - qs_zeros[g]) * qs_scales[g];
    int w = qweight[kw * N_TOT + n];

#pragma unroll
    for (int j = 0; j < 8; ++j) {
        int nib = (w >> (4 * j)) & 0xF;
        float val = (float)(nib - z) * scale;
        WH[(size_t)(kw * 8 + j) * N_TOT + n] = __float2half_rn(val);
    }
}

// ---------------------------------------------------------------------------
// x fp32 -> fp16, vectorized
// ---------------------------------------------------------------------------
__global__ void xconv_kernel(const float* __restrict__ x) {
    size_t i = ((size_t)blockIdx.x * blockDim.x + threadIdx.x) * 4;
    float4 v = *(const float4*)(x + i);
    __half2 h0 = __floats2half2_rn(v.x, v.y);
    __half2 h1 = __floats2half2_rn(v.z, v.w);
    *(__half2*)(XH + i)     = h0;
    *(__half2*)(XH + i + 2) = h1;
}

// ---------------------------------------------------------------------------
// fp16 GEMM, fp32 accumulate: out(M,N) = XH(M,K) @ WH(K,N)
// BM=BN=128, BK=32, 256 threads, double-buffered cp.async
// ---------------------------------------------------------------------------
__device__ __forceinline__ uint32_t smem_u32(const void* p) {
    return (uint32_t)__cvta_generic_to_shared(p);
}
__device__ __forceinline__ void cp_async16(uint32_t s, const void* g) {
    asm volatile("cp.async.cg.shared.global [%0], [%1], 16;\n" :: "r"(s), "l"(g));
}
__device__ __forceinline__ void cp_commit() {
    asm volatile("cp.async.commit_group;\n" ::: "memory");
}
template <int Ngrp>
__device__ __forceinline__ void cp_wait() {
    asm volatile("cp.async.wait_group %0;\n" :: "n"(Ngrp) : "memory");
}

__global__ __launch_bounds__(256, 2)
void gemm_kernel(float* __restrict__ out) {
    __shared__ __half As[2][BM][LDA];
    __shared__ __half Bs[2][BK][LDB];

    const int tid = threadIdx.x;
    const int bm = blockIdx.y * BM;
    const int bn = blockIdx.x * BN;

    const int warp = tid >> 5;
    const int lane = tid & 31;
    const int wm = (warp >> 2) * 64;   // 0 / 64
    const int wn = (warp & 3) * 32;    // 0 / 32 / 64 / 96

    float acc[4][4][4];
#pragma unroll
    for (int mi = 0; mi < 4; ++mi)
#pragma unroll
        for (int ni = 0; ni < 4; ++ni)
#pragma unroll
            for (int r = 0; r < 4; ++r) acc[mi][ni][r] = 0.f;

    // A tile: 128 rows x 32 halves = 512 x 16B chunks; chunk c -> row c/4, col (c%4)*8
    // B tile:  32 rows x 128 halves = 512 x 16B chunks; chunk c -> row c/16, col (c%16)*8
    auto prefetch = [&](int buf, int k0) {
#pragma unroll
        for (int s = 0; s < 2; ++s) {
            int c = tid + s * 256;
            int ra = c >> 2, ca = (c & 3) * 8;
            cp_async16(smem_u32(&As[buf][ra][ca]),
                       &XH[(size_t)(bm + ra) * K_TOT + k0 + ca]);
        }
#pragma unroll
        for (int s = 0; s < 2; ++s) {
            int c = tid + s * 256;
            int rb = c >> 4, cb = (c & 15) * 8;
            cp_async16(smem_u32(&Bs[buf][rb][cb]),
                       &WH[(size_t)(k0 + rb) * N_TOT + bn + cb]);
        }
        cp_commit();
    };

    prefetch(0, 0);

    for (int kt = 0; kt < NT; ++kt) {
        const int buf = kt & 1;
        if (kt + 1 < NT) {
            prefetch(buf ^ 1, (kt + 1) * BK);
            cp_wait<1>();
        } else {
            cp_wait<0>();
        }
        __syncthreads();

#pragma unroll
        for (int ks = 0; ks < BK; ks += 16) {
            uint32_t a[4][4];
#pragma unroll
            for (int mi = 0; mi < 4; ++mi) {
                uint32_t addr = smem_u32(
                    &As[buf][wm + mi * 16 + (lane & 15)][ks + (lane >> 4) * 8]);
                asm volatile(
                    "ldmatrix.sync.aligned.m8n8.x4.shared.b16 {%0,%1,%2,%3}, [%4];\n"
                    : "=r"(a[mi][0]), "=r"(a[mi][1]), "=r"(a[mi][2]), "=r"(a[mi][3])
                    : "r"(addr));
            }
            uint32_t b[4][2];
#pragma unroll
            for (int ni = 0; ni < 4; ++ni) {
                uint32_t addr = smem_u32(
                    &Bs[buf][ks + (lane & 15)][wn + ni * 8]);
                asm volatile(
                    "ldmatrix.sync.aligned.m8n8.x2.trans.shared.b16 {%0,%1}, [%2];\n"
                    : "=r"(b[ni][0]), "=r"(b[ni][1])
                    : "r"(addr));
            }
#pragma unroll
            for (int mi = 0; mi < 4; ++mi)
#pragma unroll
                for (int ni = 0; ni < 4; ++ni) {
                    asm volatile(
                        "mma.sync.aligned.m16n8k16.row.col.f32.f16.f16.f32 "
                        "{%0,%1,%2,%3}, {%4,%5,%6,%7}, {%8,%9}, {%0,%1,%2,%3};\n"
                        : "+f"(acc[mi][ni][0]), "+f"(acc[mi][ni][1]),
                          "+f"(acc[mi][ni][2]), "+f"(acc[mi][ni][3])
                        : "r"(a[mi][0]), "r"(a[mi][1]), "r"(a[mi][2]), "r"(a[mi][3]),
                          "r"(b[ni][0]), "r"(b[ni][1]));
                }
        }
        __syncthreads();
    }

    // Epilogue: m16n8 D fragment -> row r=lane/4 (and r+8), cols 2*(lane%4)+{0,1}
    const int r0 = lane >> 2;
    const int c0 = (lane & 3) * 2;
#pragma unroll
    for (int mi = 0; mi < 4; ++mi)
#pragma unroll
        for (int ni = 0; ni < 4; ++ni) {
            size_t base = (size_t)(bm + wm + mi * 16) * N_TOT + bn + wn + ni * 8;
            *(float2*)&out[base + (size_t)r0 * N_TOT + c0] =
                make_float2(acc[mi][ni][0], acc[mi][ni][1]);
            *(float2*)&out[base + (size_t)(r0 + 8) * N_TOT + c0] =
                make_float2(acc[mi][ni][2], acc[mi][ni][3]);
        }
}

// ---------------------------------------------------------------------------
extern "C" void kernel_launch(void* const* d_in, const int* in_sizes, int n_in,
                              void* d_out, int out_size) {
    const float* x        = (const float*)d_in[0];
    const int*   qweight  = (const int*)d_in[1];
    const int*   qzeros   = (const int*)d_in[2];
    const int*   qscales  = (const int*)d_in[3];
    const float* qsz      = (const float*)d_in[4];
    const float* qss      = (const float*)d_in[5];
    const int*   g_idx    = (const int*)d_in[6];
    float*       out      = (float*)d_out;

    {   // dequant W -> fp16
        int total = (K_TOT / 8) * N_TOT;
        dequant_kernel<<<(total + 255) / 256, 256>>>(qweight, qzeros, qscales,
                                                     qsz, qss, g_idx);
    }
    {   // x -> fp16
        size_t total = (size_t)M_TOT * K_TOT / 4;
        xconv_kernel<<<(unsigned)(total / 256), 256>>>(x);
    }
    {
        dim3 grid(N_TOT / BN, M_TOT / BM);
        gemm_kernel<<<grid, 256>>>(out);
    }
}